// round 6
// baseline (speedup 1.0000x reference)
#include <cuda_runtime.h>
#include <cuda_bf16.h>
#include <math.h>
#include <stdint.h>

// ---------------------------------------------------------------------------
// Problem constants
// ---------------------------------------------------------------------------
#define P_TOT   65536            // B*H*W positions (windowed layout)
#define KDIM    512
#define E_QKV   1536
#define HEADS   16
#define L_WIN   64
#define NWIN    1024

// ---------------------------------------------------------------------------
// Scratch (static device globals: allocation-free)
// ---------------------------------------------------------------------------
__device__ __nv_bfloat16 g_xhi[(size_t)P_TOT * KDIM];   // LN'd windowed input, [p][d]
__device__ __nv_bfloat16 g_xlo[(size_t)P_TOT * KDIM];
__device__ float         g_qkv[(size_t)P_TOT * E_QKV];  // qkv projection, [p][e] fp32
__device__ __nv_bfloat16 g_ahi[(size_t)P_TOT * KDIM];   // attention out, [p][d]
__device__ __nv_bfloat16 g_alo[(size_t)P_TOT * KDIM];
__device__ __nv_bfloat16 g_wqhi[E_QKV * KDIM], g_wqlo[E_QKV * KDIM];
__device__ __nv_bfloat16 g_wohi[KDIM * KDIM],  g_wolo[KDIM * KDIM];
__device__ float g_cos[L_WIN * 16];
__device__ float g_sin[L_WIN * 16];

// ---------------------------------------------------------------------------
// Helpers
// ---------------------------------------------------------------------------
__device__ __forceinline__ uint32_t smem_u32(const void* p) {
    uint32_t a;
    asm("{ .reg .u64 t; cvta.to.shared.u64 t, %1; cvt.u32.u64 %0, t; }" : "=r"(a) : "l"(p));
    return a;
}

__device__ __forceinline__ void cp16(uint32_t dst, const void* src) {
    asm volatile("cp.async.cg.shared.global [%0], [%1], 16;" :: "r"(dst), "l"(src));
}
__device__ __forceinline__ void cp_commit() {
    asm volatile("cp.async.commit_group;" ::: "memory");
}
template <int N>
__device__ __forceinline__ void cp_wait() {
    asm volatile("cp.async.wait_group %0;" :: "n"(N) : "memory");
}

__device__ __forceinline__ void ldm_x4(uint32_t* r, uint32_t addr) {
    asm volatile("ldmatrix.sync.aligned.m8n8.x4.shared.b16 {%0,%1,%2,%3}, [%4];"
                 : "=r"(r[0]), "=r"(r[1]), "=r"(r[2]), "=r"(r[3]) : "r"(addr));
}

__device__ __forceinline__ void mma_bf16(float* c, const uint32_t* a, const uint32_t* b) {
    asm volatile(
        "mma.sync.aligned.m16n8k16.row.col.f32.bf16.bf16.f32 "
        "{%0,%1,%2,%3}, {%4,%5,%6,%7}, {%8,%9}, {%0,%1,%2,%3};"
        : "+f"(c[0]), "+f"(c[1]), "+f"(c[2]), "+f"(c[3])
        : "r"(a[0]), "r"(a[1]), "r"(a[2]), "r"(a[3]), "r"(b[0]), "r"(b[1]));
}

// ---------------------------------------------------------------------------
// RoPE table init
// ---------------------------------------------------------------------------
__global__ void rope_init_kernel() {
    int idx = threadIdx.x;
    for (; idx < L_WIN * 16; idx += blockDim.x) {
        int l = idx >> 4;
        int q = idx & 15;
        int i = l >> 3;
        int j = l & 7;
        float pos, e;
        if (q < 8) { pos = (float)i; e = (float)q; }
        else       { pos = (float)j; e = (float)(q - 8); }
        float freq  = powf(10000.0f, -e / 8.0f);
        float theta = pos * freq;
        g_cos[idx] = cosf(theta);
        g_sin[idx] = sinf(theta);
    }
}

// ---------------------------------------------------------------------------
// fp32 -> bf16 hi/lo split for weights
// ---------------------------------------------------------------------------
__global__ void convw_kernel(const float* __restrict__ w,
                             __nv_bfloat16* __restrict__ hi,
                             __nv_bfloat16* __restrict__ lo, int n) {
    int i = blockIdx.x * 256 + threadIdx.x;
    if (i < n) {
        float v = w[i];
        __nv_bfloat16 h = __float2bfloat16(v);
        hi[i] = h;
        lo[i] = __float2bfloat16(v - __bfloat162float(h));
    }
}

// ---------------------------------------------------------------------------
// LayerNorm + roll(-4,-4) + window partition -> x hi/lo bf16 in [p][d] layout
// ---------------------------------------------------------------------------
__global__ void __launch_bounds__(256) ln_window_kernel(
    const float* __restrict__ x,
    const float* __restrict__ ln_g,
    const float* __restrict__ ln_b)
{
    int blk = blockIdx.x;
    int w0  = (blk & 3) * 32;
    int h   = (blk >> 2) & 127;
    int bb  = blk >> 9;

    int px  = threadIdx.x & 31;
    int grp = threadIdx.x >> 5;
    int w   = w0 + px;

    __shared__ float sh_s[8][32], sh_s2[8][32];
    __shared__ float sh_m[32], sh_r[32];
    __shared__ int   sh_p[32];
    __shared__ float sh_g[512], sh_b[512];
    __shared__ float sh_t[32][132];

    for (int d = threadIdx.x; d < 512; d += 256) {
        sh_g[d] = ln_g[d];
        sh_b[d] = ln_b[d];
    }

    size_t base = (size_t)bb * (512u * 16384u) + (size_t)h * 128 + w;

    float vals[64];
    float s = 0.f, s2 = 0.f;
    #pragma unroll 8
    for (int i = 0; i < 64; i++) {
        float v = x[base + (size_t)(grp + 8 * i) * 16384];
        vals[i] = v;
        s += v; s2 += v * v;
    }

    sh_s[grp][px] = s; sh_s2[grp][px] = s2;
    if (grp == 0) {
        int hs  = (h - 4) & 127;
        int ws  = (w - 4) & 127;
        int wdx = bb * 256 + (hs >> 3) * 16 + (ws >> 3);
        sh_p[px] = wdx * 64 + (hs & 7) * 8 + (ws & 7);
    }
    __syncthreads();
    if (threadIdx.x < 32) {
        float ts = 0.f, ts2 = 0.f;
        #pragma unroll
        for (int g2 = 0; g2 < 8; g2++) { ts += sh_s[g2][threadIdx.x]; ts2 += sh_s2[g2][threadIdx.x]; }
        float mean = ts * (1.0f / 512.0f);
        float var  = ts2 * (1.0f / 512.0f) - mean * mean;
        sh_m[threadIdx.x] = mean;
        sh_r[threadIdx.x] = rsqrtf(var + 1e-5f);
    }
    __syncthreads();

    float mean = sh_m[px], r = sh_r[px];

    int pl = threadIdx.x >> 3;
    int jj = threadIdx.x & 7;

    for (int c = 0; c < 4; c++) {
        #pragma unroll
        for (int ii = 0; ii < 16; ii++) {
            int d = c * 128 + grp + 8 * ii;
            float xn = (vals[c * 16 + ii] - mean) * r * sh_g[d] + sh_b[d];
            sh_t[px][grp + 8 * ii] = xn;
        }
        __syncthreads();

        size_t dst = (size_t)sh_p[pl] * 512 + c * 128 + jj * 16;
        __nv_bfloat162 hv[8], lv[8];
        #pragma unroll
        for (int t2 = 0; t2 < 8; t2++) {
            float a  = sh_t[pl][jj * 16 + 2 * t2];
            float b2 = sh_t[pl][jj * 16 + 2 * t2 + 1];
            __nv_bfloat16 ah = __float2bfloat16(a);
            __nv_bfloat16 bh = __float2bfloat16(b2);
            hv[t2].x = ah; hv[t2].y = bh;
            lv[t2].x = __float2bfloat16(a  - __bfloat162float(ah));
            lv[t2].y = __float2bfloat16(b2 - __bfloat162float(bh));
        }
        *(uint4*)(g_xhi + dst)     = ((uint4*)hv)[0];
        *(uint4*)(g_xhi + dst + 8) = ((uint4*)hv)[1];
        *(uint4*)(g_xlo + dst)     = ((uint4*)lv)[0];
        *(uint4*)(g_xlo + dst + 8) = ((uint4*)lv)[1];
        __syncthreads();
    }
}

// ---------------------------------------------------------------------------
// HMMA bf16-split GEMM: C = (Ahi+Alo) * (Bhi+Blo)^T, 3 passes.
// CTA tile 128(m) x 256(n), BK=32, 8 warps (2m x 4n), warp tile 64x64,
// 3-stage cp.async pipeline.
// MODE 0: smem-transposed epilogue -> C[p][e] fp32 (row width EW).
// MODE 1: +bias, window-inverse + roll scatter (float2 stores).
// ---------------------------------------------------------------------------
#define ROWB     80
#define OFF_AH   0
#define OFF_AL   (128 * ROWB)              // 10240
#define OFF_BH   (2 * 128 * ROWB)          // 20480
#define OFF_BL   (OFF_BH + 256 * ROWB)     // 40960
#define STAGE_SZ (OFF_BL + 256 * ROWB)     // 61440
#define SM_GEMM  (3 * STAGE_SZ)            // 184320

template <int MODE>
__global__ void __launch_bounds__(256, 1) gemm_hmma(
    const __nv_bfloat16* __restrict__ Ahi, const __nv_bfloat16* __restrict__ Alo,
    const __nv_bfloat16* __restrict__ Bhi, const __nv_bfloat16* __restrict__ Blo,
    float* __restrict__ C, const float* __restrict__ bias, int EW)
{
    extern __shared__ __align__(128) char sm[];
    uint32_t smb = smem_u32(sm);

    const int tid  = threadIdx.x;
    const int wid  = tid >> 5;
    const int lane = tid & 31;
    const int bm   = blockIdx.x * 128;
    const int bn   = blockIdx.y * 256;
    const int wm   = (wid >> 2) * 64;     // 0 / 64
    const int wn   = (wid & 3) * 64;      // 0 / 64 / 128 / 192

    float acc[4][8][4];
    #pragma unroll
    for (int i = 0; i < 4; i++)
        #pragma unroll
        for (int j = 0; j < 8; j++)
            #pragma unroll
            for (int q = 0; q < 4; q++) acc[i][j][q] = 0.f;

    const int l7  = lane & 7;
    const int sel = lane >> 3;
    const int a_r = (sel & 1) * 8 + l7;
    const int a_k = (sel >> 1) * 16;
    const int b_r = (sel >> 1) * 8 + l7;
    const int b_k = (sel & 1) * 16;

    auto load_stage = [&](int ch, int st) {
        const size_t gk = (size_t)ch * 64;      // 32 bf16 = 64 bytes
        uint32_t sb = smb + st * STAGE_SZ;
        // A: 128 rows x 4 x 16B (hi & lo)
        #pragma unroll
        for (int i = 0; i < 2; i++) {
            int slot = tid + i * 256;            // 0..511
            int row  = slot >> 2;
            int cb   = (slot & 3) * 16;
            uint32_t dof = row * ROWB + cb;
            size_t   sof = (size_t)(bm + row) * 1024 + gk + cb;
            cp16(sb + OFF_AH + dof, (const char*)Ahi + sof);
            cp16(sb + OFF_AL + dof, (const char*)Alo + sof);
        }
        // B: 256 rows x 4 x 16B (hi & lo)
        #pragma unroll
        for (int i = 0; i < 4; i++) {
            int slot = tid + i * 256;            // 0..1023
            int row  = slot >> 2;
            int cb   = (slot & 3) * 16;
            uint32_t dof = row * ROWB + cb;
            size_t   sof = (size_t)(bn + row) * 1024 + gk + cb;
            cp16(sb + OFF_BH + dof, (const char*)Bhi + sof);
            cp16(sb + OFF_BL + dof, (const char*)Blo + sof);
        }
        cp_commit();
    };

    load_stage(0, 0);
    load_stage(1, 1);

    #pragma unroll 1
    for (int ch = 0; ch < 16; ch++) {
        if (ch < 14) {
            load_stage(ch + 2, (ch + 2) % 3);
            cp_wait<2>();
        } else if (ch == 14) {
            cp_wait<1>();
        } else {
            cp_wait<0>();
        }
        __syncthreads();

        uint32_t sb  = smb + (ch % 3) * STAGE_SZ;
        uint32_t aAH = sb + OFF_AH + (wm + a_r) * ROWB + a_k;
        uint32_t aAL = sb + OFF_AL + (wm + a_r) * ROWB + a_k;
        uint32_t aBH = sb + OFF_BH + (wn + b_r) * ROWB + b_k;
        uint32_t aBL = sb + OFF_BL + (wn + b_r) * ROWB + b_k;

        #pragma unroll
        for (int ks = 0; ks < 2; ks++) {
            int kb = ks * 32;
            uint32_t ah[4][4], al[4][4];
            #pragma unroll
            for (int mt = 0; mt < 4; mt++) {
                ldm_x4(ah[mt], aAH + mt * (16 * ROWB) + kb);
                ldm_x4(al[mt], aAL + mt * (16 * ROWB) + kb);
            }
            #pragma unroll
            for (int np = 0; np < 4; np++) {
                uint32_t bh[4], bl[4];
                ldm_x4(bh, aBH + np * (16 * ROWB) + kb);
                ldm_x4(bl, aBL + np * (16 * ROWB) + kb);
                #pragma unroll
                for (int mt = 0; mt < 4; mt++) {
                    mma_bf16(acc[mt][2 * np],     ah[mt], bh);
                    mma_bf16(acc[mt][2 * np + 1], ah[mt], bh + 2);
                    mma_bf16(acc[mt][2 * np],     ah[mt], bl);
                    mma_bf16(acc[mt][2 * np + 1], ah[mt], bl + 2);
                    mma_bf16(acc[mt][2 * np],     al[mt], bh);
                    mma_bf16(acc[mt][2 * np + 1], al[mt], bh + 2);
                }
            }
        }
        __syncthreads();
    }

    // ------------------------------ epilogue ------------------------------
    if (MODE == 0) {
        // transpose through smem -> C[p][e] (two 128-position halves)
        float* smt = (float*)sm;   // [128 p][132 e]
        #pragma unroll 1
        for (int half = 0; half < 2; half++) {
            if ((wn >> 7) == half) {
                int pbase = wn & 127;   // FIX: was wn & 63 (warp collision)
                #pragma unroll
                for (int mt = 0; mt < 4; mt++) {
                    #pragma unroll
                    for (int nt = 0; nt < 8; nt++) {
                        int e0  = wm + (lane >> 2) + mt * 16;
                        int pl0 = pbase + (lane & 3) * 2 + nt * 8;
                        smt[(pl0)     * 132 + e0]     = acc[mt][nt][0];
                        smt[(pl0 + 1) * 132 + e0]     = acc[mt][nt][1];
                        smt[(pl0)     * 132 + e0 + 8] = acc[mt][nt][2];
                        smt[(pl0 + 1) * 132 + e0 + 8] = acc[mt][nt][3];
                    }
                }
            }
            __syncthreads();
            int r0 = tid >> 5;
            int c4 = lane * 4;
            #pragma unroll
            for (int i = 0; i < 16; i++) {
                int row = r0 + i * 8;
                float4 v = *(float4*)&smt[row * 132 + c4];
                *(float4*)(C + (size_t)(bn + half * 128 + row) * EW + bm + c4) = v;
            }
            __syncthreads();
        }
    } else {
        const int mrow0 = bm + wm + (lane >> 2);
        const int ncol0 = bn + wn + (lane & 3) * 2;
        #pragma unroll
        for (int mt = 0; mt < 4; mt++) {
            float bo0 = bias[mrow0 + mt * 16];
            float bo1 = bias[mrow0 + mt * 16 + 8];
            #pragma unroll
            for (int nt = 0; nt < 8; nt++) {
                int p   = ncol0 + nt * 8;       // even; p+1 in same window row
                int wdx = p >> 6, l = p & 63;
                int bb  = wdx >> 8, rem = wdx & 255;
                int hs  = ((rem >> 4) << 3) + (l >> 3);
                int ws  = ((rem & 15) << 3) + (l & 7);
                int hh  = (hs + 4) & 127;
                int ww  = (ws + 4) & 127;
                #pragma unroll
                for (int qh = 0; qh < 2; qh++) {
                    int m = mrow0 + mt * 16 + qh * 8;
                    float bo = qh ? bo1 : bo0;
                    size_t idx = (((size_t)bb * 512 + m) << 14) + (hh << 7) + ww;
                    *(float2*)(C + idx) =
                        make_float2(acc[mt][nt][2 * qh] + bo, acc[mt][nt][2 * qh + 1] + bo);
                }
            }
        }
    }
}

// ---------------------------------------------------------------------------
// Attention per (window, head). Reads g_qkv [p][e]; writes att hi/lo bf16
// [p][d]. 64 threads; thread t owns position row p0+t. 4-chunk flash softmax.
// ---------------------------------------------------------------------------
__global__ void __launch_bounds__(64) attn_kernel() {
    int win = blockIdx.x;
    int h   = blockIdx.y;
    int t   = threadIdx.x;

    __shared__ float ks[L_WIN][36];
    __shared__ float vs[L_WIN][36];

    int p = win * 64 + t;
    const float* rowq = g_qkv + (size_t)p * E_QKV + h * 32;

    float qr[32];
    #pragma unroll
    for (int i = 0; i < 8; i++) *(float4*)(qr + 4 * i) = *(const float4*)(rowq + 4 * i);

    {
        float kr[32], vr[32];
        #pragma unroll
        for (int i = 0; i < 8; i++) *(float4*)(kr + 4 * i) = *(const float4*)(rowq + 512 + 4 * i);
        #pragma unroll
        for (int i = 0; i < 8; i++) *(float4*)(vr + 4 * i) = *(const float4*)(rowq + 1024 + 4 * i);

        const float scale = 0.17677669529663687f;   // 32^-0.5
        #pragma unroll
        for (int d = 0; d < 16; d++) {
            float c = g_cos[t * 16 + d];
            float s = g_sin[t * 16 + d];
            float q1 = qr[d], q2 = qr[d + 16];
            qr[d]      = (q1 * c - q2 * s) * scale;
            qr[d + 16] = (q2 * c + q1 * s) * scale;
            float k1 = kr[d], k2 = kr[d + 16];
            kr[d]      = k1 * c - k2 * s;
            kr[d + 16] = k2 * c + k1 * s;
        }
        #pragma unroll
        for (int d = 0; d < 32; d++) { ks[t][d] = kr[d]; vs[t][d] = vr[d]; }
    }
    __syncthreads();

    float m = -1e30f, ssum = 0.f;
    float oacc[32];
    #pragma unroll
    for (int d = 0; d < 32; d++) oacc[d] = 0.f;

    #pragma unroll 1
    for (int c0 = 0; c0 < 64; c0 += 16) {
        float lo[16];
        float mc = -1e30f;
        #pragma unroll
        for (int j = 0; j < 16; j++) {
            float s = 0.f;
            #pragma unroll
            for (int d = 0; d < 32; d++) s += qr[d] * ks[c0 + j][d];
            lo[j] = s;
            mc = fmaxf(mc, s);
        }
        float mn = fmaxf(m, mc);
        float f  = __expf(m - mn);
        ssum *= f;
        #pragma unroll
        for (int d = 0; d < 32; d++) oacc[d] *= f;
        #pragma unroll
        for (int j = 0; j < 16; j++) {
            float e = __expf(lo[j] - mn);
            ssum += e;
            #pragma unroll
            for (int d = 0; d < 32; d++) oacc[d] += e * vs[c0 + j][d];
        }
        m = mn;
    }
    float inv = 1.f / ssum;

    size_t ob = (size_t)p * 512 + (size_t)h * 32;
    #pragma unroll
    for (int d = 0; d < 16; d++) {
        float a  = oacc[2 * d] * inv;
        float b2 = oacc[2 * d + 1] * inv;
        __nv_bfloat16 ah = __float2bfloat16(a);
        __nv_bfloat16 bh = __float2bfloat16(b2);
        __nv_bfloat162 hv; hv.x = ah; hv.y = bh;
        __nv_bfloat162 lv;
        lv.x = __float2bfloat16(a  - __bfloat162float(ah));
        lv.y = __float2bfloat16(b2 - __bfloat162float(bh));
        ((__nv_bfloat162*)(g_ahi + ob))[d] = hv;
        ((__nv_bfloat162*)(g_alo + ob))[d] = lv;
    }
}

// ---------------------------------------------------------------------------
// Launch
// ---------------------------------------------------------------------------
extern "C" void kernel_launch(void* const* d_in, const int* in_sizes, int n_in,
                              void* d_out, int out_size)
{
    const float* x     = (const float*)d_in[0];
    const float* ln_g  = (const float*)d_in[1];
    const float* ln_b  = (const float*)d_in[2];
    const float* w_qkv = (const float*)d_in[3];
    const float* w_out = (const float*)d_in[4];
    const float* b_out = (const float*)d_in[5];
    float* out = (float*)d_out;

    cudaFuncSetAttribute(gemm_hmma<0>, cudaFuncAttributeMaxDynamicSharedMemorySize, SM_GEMM);
    cudaFuncSetAttribute(gemm_hmma<1>, cudaFuncAttributeMaxDynamicSharedMemorySize, SM_GEMM);

    float *qkv;
    __nv_bfloat16 *xhi, *xlo, *ahi, *alo, *wqhi, *wqlo, *wohi, *wolo;
    cudaGetSymbolAddress((void**)&qkv,  g_qkv);
    cudaGetSymbolAddress((void**)&xhi,  g_xhi);
    cudaGetSymbolAddress((void**)&xlo,  g_xlo);
    cudaGetSymbolAddress((void**)&ahi,  g_ahi);
    cudaGetSymbolAddress((void**)&alo,  g_alo);
    cudaGetSymbolAddress((void**)&wqhi, g_wqhi);
    cudaGetSymbolAddress((void**)&wqlo, g_wqlo);
    cudaGetSymbolAddress((void**)&wohi, g_wohi);
    cudaGetSymbolAddress((void**)&wolo, g_wolo);

    rope_init_kernel<<<1, 512>>>();
    convw_kernel<<<(E_QKV * KDIM + 255) / 256, 256>>>(w_qkv, wqhi, wqlo, E_QKV * KDIM);
    convw_kernel<<<(KDIM * KDIM + 255) / 256, 256>>>(w_out, wohi, wolo, KDIM * KDIM);
    ln_window_kernel<<<2048, 256>>>(x, ln_g, ln_b);

    {
        dim3 grid(E_QKV / 128, P_TOT / 256);   // (12, 256), bm fastest for L2 reuse
        gemm_hmma<0><<<grid, 256, SM_GEMM>>>(wqhi, wqlo, xhi, xlo, qkv, nullptr, E_QKV);
    }

    {
        dim3 grid(NWIN, HEADS);
        attn_kernel<<<grid, 64>>>();
    }

    {
        dim3 grid(KDIM / 128, P_TOT / 256);    // (4, 256)
        gemm_hmma<1><<<grid, 256, SM_GEMM>>>(wohi, wolo, ahi, alo, out, b_out, 0);
    }
}

// round 7
// speedup vs baseline: 1.3731x; 1.3731x over previous
#include <cuda_runtime.h>
#include <cuda_fp16.h>
#include <math.h>
#include <stdint.h>

// ---------------------------------------------------------------------------
// Problem constants
// ---------------------------------------------------------------------------
#define P_TOT   65536            // B*H*W positions (windowed layout)
#define KDIM    512
#define E_QKV   1536
#define HEADS   16
#define L_WIN   64
#define NWIN    1024

// ---------------------------------------------------------------------------
// Scratch (static device globals: allocation-free)
// ---------------------------------------------------------------------------
__device__ __half g_xh [(size_t)P_TOT * KDIM];          // LN'd windowed input, [p][d] fp16
__device__ float  g_qkv[(size_t)P_TOT * E_QKV];         // qkv projection, [p][e] fp32
__device__ __half g_ah [(size_t)P_TOT * KDIM];          // attention out, [p][d] fp16
__device__ __half g_wqhi[E_QKV * KDIM], g_wqlo[E_QKV * KDIM];
__device__ __half g_wohi[KDIM * KDIM],  g_wolo[KDIM * KDIM];
__device__ float g_cos[L_WIN * 16];
__device__ float g_sin[L_WIN * 16];

// ---------------------------------------------------------------------------
// Helpers
// ---------------------------------------------------------------------------
__device__ __forceinline__ uint32_t smem_u32(const void* p) {
    uint32_t a;
    asm("{ .reg .u64 t; cvta.to.shared.u64 t, %1; cvt.u32.u64 %0, t; }" : "=r"(a) : "l"(p));
    return a;
}

__device__ __forceinline__ void cp16(uint32_t dst, const void* src) {
    asm volatile("cp.async.cg.shared.global [%0], [%1], 16;" :: "r"(dst), "l"(src));
}
__device__ __forceinline__ void cp_commit() {
    asm volatile("cp.async.commit_group;" ::: "memory");
}
template <int N>
__device__ __forceinline__ void cp_wait() {
    asm volatile("cp.async.wait_group %0;" :: "n"(N) : "memory");
}

__device__ __forceinline__ void ldm_x4(uint32_t* r, uint32_t addr) {
    asm volatile("ldmatrix.sync.aligned.m8n8.x4.shared.b16 {%0,%1,%2,%3}, [%4];"
                 : "=r"(r[0]), "=r"(r[1]), "=r"(r[2]), "=r"(r[3]) : "r"(addr));
}

__device__ __forceinline__ void mma_f16(float* c, const uint32_t* a, const uint32_t* b) {
    asm volatile(
        "mma.sync.aligned.m16n8k16.row.col.f32.f16.f16.f32 "
        "{%0,%1,%2,%3}, {%4,%5,%6,%7}, {%8,%9}, {%0,%1,%2,%3};"
        : "+f"(c[0]), "+f"(c[1]), "+f"(c[2]), "+f"(c[3])
        : "r"(a[0]), "r"(a[1]), "r"(a[2]), "r"(a[3]), "r"(b[0]), "r"(b[1]));
}

// ---------------------------------------------------------------------------
// RoPE table init
// ---------------------------------------------------------------------------
__global__ void rope_init_kernel() {
    int idx = threadIdx.x;
    for (; idx < L_WIN * 16; idx += blockDim.x) {
        int l = idx >> 4;
        int q = idx & 15;
        int i = l >> 3;
        int j = l & 7;
        float pos, e;
        if (q < 8) { pos = (float)i; e = (float)q; }
        else       { pos = (float)j; e = (float)(q - 8); }
        float freq  = powf(10000.0f, -e / 8.0f);
        float theta = pos * freq;
        g_cos[idx] = cosf(theta);
        g_sin[idx] = sinf(theta);
    }
}

// ---------------------------------------------------------------------------
// fp32 -> fp16 hi/lo split for weights (near-exact 2-term decomposition)
// ---------------------------------------------------------------------------
__global__ void convw_kernel(const float* __restrict__ w,
                             __half* __restrict__ hi,
                             __half* __restrict__ lo, int n) {
    int i = blockIdx.x * 256 + threadIdx.x;
    if (i < n) {
        float v = w[i];
        __half h = __float2half_rn(v);
        hi[i] = h;
        lo[i] = __float2half_rn(v - __half2float(h));
    }
}

// ---------------------------------------------------------------------------
// LayerNorm + roll(-4,-4) + window partition -> x fp16 in [p][d] layout
// ---------------------------------------------------------------------------
__global__ void __launch_bounds__(256) ln_window_kernel(
    const float* __restrict__ x,
    const float* __restrict__ ln_g,
    const float* __restrict__ ln_b)
{
    int blk = blockIdx.x;
    int w0  = (blk & 3) * 32;
    int h   = (blk >> 2) & 127;
    int bb  = blk >> 9;

    int px  = threadIdx.x & 31;
    int grp = threadIdx.x >> 5;
    int w   = w0 + px;

    __shared__ float sh_s[8][32], sh_s2[8][32];
    __shared__ float sh_m[32], sh_r[32];
    __shared__ int   sh_p[32];
    __shared__ float sh_g[512], sh_b[512];
    __shared__ float sh_t[32][132];

    for (int d = threadIdx.x; d < 512; d += 256) {
        sh_g[d] = ln_g[d];
        sh_b[d] = ln_b[d];
    }

    size_t base = (size_t)bb * (512u * 16384u) + (size_t)h * 128 + w;

    float vals[64];
    float s = 0.f, s2 = 0.f;
    #pragma unroll 8
    for (int i = 0; i < 64; i++) {
        float v = x[base + (size_t)(grp + 8 * i) * 16384];
        vals[i] = v;
        s += v; s2 += v * v;
    }

    sh_s[grp][px] = s; sh_s2[grp][px] = s2;
    if (grp == 0) {
        int hs  = (h - 4) & 127;
        int ws  = (w - 4) & 127;
        int wdx = bb * 256 + (hs >> 3) * 16 + (ws >> 3);
        sh_p[px] = wdx * 64 + (hs & 7) * 8 + (ws & 7);
    }
    __syncthreads();
    if (threadIdx.x < 32) {
        float ts = 0.f, ts2 = 0.f;
        #pragma unroll
        for (int g2 = 0; g2 < 8; g2++) { ts += sh_s[g2][threadIdx.x]; ts2 += sh_s2[g2][threadIdx.x]; }
        float mean = ts * (1.0f / 512.0f);
        float var  = ts2 * (1.0f / 512.0f) - mean * mean;
        sh_m[threadIdx.x] = mean;
        sh_r[threadIdx.x] = rsqrtf(var + 1e-5f);
    }
    __syncthreads();

    float mean = sh_m[px], r = sh_r[px];

    int pl = threadIdx.x >> 3;
    int jj = threadIdx.x & 7;

    for (int c = 0; c < 4; c++) {
        #pragma unroll
        for (int ii = 0; ii < 16; ii++) {
            int d = c * 128 + grp + 8 * ii;
            float xn = (vals[c * 16 + ii] - mean) * r * sh_g[d] + sh_b[d];
            sh_t[px][grp + 8 * ii] = xn;
        }
        __syncthreads();

        size_t dst = (size_t)sh_p[pl] * 512 + c * 128 + jj * 16;
        __half2 hv[8];
        #pragma unroll
        for (int t2 = 0; t2 < 8; t2++) {
            hv[t2] = __floats2half2_rn(sh_t[pl][jj * 16 + 2 * t2],
                                       sh_t[pl][jj * 16 + 2 * t2 + 1]);
        }
        *(uint4*)(g_xh + dst) = ((uint4*)hv)[0];
        *(uint4*)(g_xh + dst + 8) = ((uint4*)hv)[1];
        __syncthreads();
    }
}

// ---------------------------------------------------------------------------
// HMMA fp16 2-pass GEMM: C = (Ahi+Alo) * B^T  (A = weight split, B = fp16 act)
// CTA tile 128x128, BK=32, 8 warps (2x4), warp tile 64x32, double-buffered
// cp.async. MODE 0: smem-transposed -> C[p][e] fp32. MODE 1: +bias, scatter.
// ---------------------------------------------------------------------------
#define ROWB     80
#define OFF_AH   0
#define OFF_AL   (128 * ROWB)              // 10240
#define OFF_B    (2 * 128 * ROWB)          // 20480
#define STAGE_SZ (3 * 128 * ROWB)          // 30720
#define SM_GEMM  69632                     // max(2*STAGE_SZ, 128*132*4 transpose)

template <int MODE>
__global__ void __launch_bounds__(256) gemm_hmma(
    const __half* __restrict__ Ahi, const __half* __restrict__ Alo,
    const __half* __restrict__ B,
    float* __restrict__ C, const float* __restrict__ bias, int EW)
{
    extern __shared__ __align__(128) char sm[];
    uint32_t smb = smem_u32(sm);

    const int tid  = threadIdx.x;
    const int wid  = tid >> 5;
    const int lane = tid & 31;
    const int bm   = blockIdx.x * 128;
    const int bn   = blockIdx.y * 128;
    const int wm   = (wid >> 2) * 64;
    const int wn   = (wid & 3) * 32;

    const int lrow = tid >> 2;           // 0..63
    const int lch  = (tid & 3) * 16;     // 0/16/32/48

    const char* pAh = (const char*)Ahi + (size_t)(bm + lrow) * 1024 + lch;
    const char* pAl = (const char*)Alo + (size_t)(bm + lrow) * 1024 + lch;
    const char* pB  = (const char*)B   + (size_t)(bn + lrow) * 1024 + lch;

    float acc[4][4][4];
    #pragma unroll
    for (int i = 0; i < 4; i++)
        #pragma unroll
        for (int j = 0; j < 4; j++)
            #pragma unroll
            for (int q = 0; q < 4; q++) acc[i][j][q] = 0.f;

    const int l7  = lane & 7;
    const int sel = lane >> 3;
    const int a_r = (sel & 1) * 8 + l7;
    const int a_k = (sel >> 1) * 16;
    const int b_r = (sel >> 1) * 8 + l7;
    const int b_k = (sel & 1) * 16;

    auto load_stage = [&](int ch, int st) {
        const size_t gk = (size_t)ch * 64;
        uint32_t sb = smb + st * STAGE_SZ;
        #pragma unroll
        for (int r = 0; r < 2; r++) {
            int row = lrow + r * 64;
            uint32_t dof = row * ROWB + lch;
            size_t   sof = gk + (size_t)r * 64 * 1024;
            cp16(sb + OFF_AH + dof, pAh + sof);
            cp16(sb + OFF_AL + dof, pAl + sof);
            cp16(sb + OFF_B  + dof, pB  + sof);
        }
        cp_commit();
    };

    load_stage(0, 0);

    #pragma unroll 1
    for (int ch = 0; ch < 16; ch++) {
        if (ch < 15) {
            load_stage(ch + 1, (ch + 1) & 1);
            cp_wait<1>();
        } else {
            cp_wait<0>();
        }
        __syncthreads();

        uint32_t sb  = smb + (ch & 1) * STAGE_SZ;
        uint32_t aAH = sb + OFF_AH + (wm + a_r) * ROWB + a_k;
        uint32_t aAL = sb + OFF_AL + (wm + a_r) * ROWB + a_k;
        uint32_t aB  = sb + OFF_B  + (wn + b_r) * ROWB + b_k;

        #pragma unroll
        for (int ks = 0; ks < 2; ks++) {
            int kb = ks * 32;
            uint32_t ah[4][4], al[4][4], bf[4][2];
            #pragma unroll
            for (int mt = 0; mt < 4; mt++) {
                ldm_x4(ah[mt], aAH + mt * (16 * ROWB) + kb);
                ldm_x4(al[mt], aAL + mt * (16 * ROWB) + kb);
            }
            #pragma unroll
            for (int np = 0; np < 2; np++) {
                uint32_t t4[4];
                ldm_x4(t4, aB + np * (16 * ROWB) + kb);
                bf[2 * np][0] = t4[0]; bf[2 * np][1] = t4[1];
                bf[2 * np + 1][0] = t4[2]; bf[2 * np + 1][1] = t4[3];
            }
            #pragma unroll
            for (int mt = 0; mt < 4; mt++)
                #pragma unroll
                for (int nt = 0; nt < 4; nt++)
                    mma_f16(acc[mt][nt], ah[mt], bf[nt]);
            #pragma unroll
            for (int mt = 0; mt < 4; mt++)
                #pragma unroll
                for (int nt = 0; nt < 4; nt++)
                    mma_f16(acc[mt][nt], al[mt], bf[nt]);
        }
        __syncthreads();
    }

    // ------------------------------ epilogue ------------------------------
    const int mrow0 = bm + wm + (lane >> 2);
    const int ncol0 = bn + wn + (lane & 3) * 2;

    if (MODE == 0) {
        // transpose through smem -> C[p][e], row width EW
        float* smt = (float*)sm;   // [128 p][132 e]
        #pragma unroll
        for (int mt = 0; mt < 4; mt++) {
            #pragma unroll
            for (int nt = 0; nt < 4; nt++) {
                int e0  = wm + (lane >> 2) + mt * 16;
                int pl0 = wn + (lane & 3) * 2 + nt * 8;
                smt[(pl0)     * 132 + e0]     = acc[mt][nt][0];
                smt[(pl0 + 1) * 132 + e0]     = acc[mt][nt][1];
                smt[(pl0)     * 132 + e0 + 8] = acc[mt][nt][2];
                smt[(pl0 + 1) * 132 + e0 + 8] = acc[mt][nt][3];
            }
        }
        __syncthreads();
        int r0 = tid >> 5;
        int c4 = lane * 4;
        #pragma unroll
        for (int i = 0; i < 16; i++) {
            int row = r0 + i * 8;
            float4 v = *(float4*)&smt[row * 132 + c4];
            *(float4*)(C + (size_t)(bn + row) * EW + bm + c4) = v;
        }
    } else {
        #pragma unroll
        for (int mt = 0; mt < 4; mt++) {
            float bo0 = bias[mrow0 + mt * 16];
            float bo1 = bias[mrow0 + mt * 16 + 8];
            #pragma unroll
            for (int nt = 0; nt < 4; nt++) {
                int p   = ncol0 + nt * 8;       // even; p+1 in same window row
                int wdx = p >> 6, l = p & 63;
                int bb  = wdx >> 8, rem = wdx & 255;
                int hs  = ((rem >> 4) << 3) + (l >> 3);
                int ws  = ((rem & 15) << 3) + (l & 7);
                int hh  = (hs + 4) & 127;
                int ww  = (ws + 4) & 127;
                #pragma unroll
                for (int qh = 0; qh < 2; qh++) {
                    int m = mrow0 + mt * 16 + qh * 8;
                    float bo = qh ? bo1 : bo0;
                    size_t idx = (((size_t)bb * 512 + m) << 14) + (hh << 7) + ww;
                    *(float2*)(C + idx) =
                        make_float2(acc[mt][nt][2 * qh] + bo, acc[mt][nt][2 * qh + 1] + bo);
                }
            }
        }
    }
}

// ---------------------------------------------------------------------------
// Attention per (window, head). Reads g_qkv [p][e]; writes att fp16 [p][d].
// 64 threads; thread t owns position row p0+t. 4-chunk flash softmax.
// ---------------------------------------------------------------------------
__global__ void __launch_bounds__(64) attn_kernel() {
    int win = blockIdx.x;
    int h   = blockIdx.y;
    int t   = threadIdx.x;

    __shared__ float ks[L_WIN][36];
    __shared__ float vs[L_WIN][36];

    int p = win * 64 + t;
    const float* rowq = g_qkv + (size_t)p * E_QKV + h * 32;

    float qr[32];
    #pragma unroll
    for (int i = 0; i < 8; i++) *(float4*)(qr + 4 * i) = *(const float4*)(rowq + 4 * i);

    {
        float kr[32], vr[32];
        #pragma unroll
        for (int i = 0; i < 8; i++) *(float4*)(kr + 4 * i) = *(const float4*)(rowq + 512 + 4 * i);
        #pragma unroll
        for (int i = 0; i < 8; i++) *(float4*)(vr + 4 * i) = *(const float4*)(rowq + 1024 + 4 * i);

        const float scale = 0.17677669529663687f;   // 32^-0.5
        #pragma unroll
        for (int d = 0; d < 16; d++) {
            float c = g_cos[t * 16 + d];
            float s = g_sin[t * 16 + d];
            float q1 = qr[d], q2 = qr[d + 16];
            qr[d]      = (q1 * c - q2 * s) * scale;
            qr[d + 16] = (q2 * c + q1 * s) * scale;
            float k1 = kr[d], k2 = kr[d + 16];
            kr[d]      = k1 * c - k2 * s;
            kr[d + 16] = k2 * c + k1 * s;
        }
        #pragma unroll
        for (int d = 0; d < 32; d++) { ks[t][d] = kr[d]; vs[t][d] = vr[d]; }
    }
    __syncthreads();

    float m = -1e30f, ssum = 0.f;
    float oacc[32];
    #pragma unroll
    for (int d = 0; d < 32; d++) oacc[d] = 0.f;

    #pragma unroll 1
    for (int c0 = 0; c0 < 64; c0 += 16) {
        float lo[16];
        float mc = -1e30f;
        #pragma unroll
        for (int j = 0; j < 16; j++) {
            float s = 0.f;
            #pragma unroll
            for (int d = 0; d < 32; d++) s += qr[d] * ks[c0 + j][d];
            lo[j] = s;
            mc = fmaxf(mc, s);
        }
        float mn = fmaxf(m, mc);
        float f  = __expf(m - mn);
        ssum *= f;
        #pragma unroll
        for (int d = 0; d < 32; d++) oacc[d] *= f;
        #pragma unroll
        for (int j = 0; j < 16; j++) {
            float e = __expf(lo[j] - mn);
            ssum += e;
            #pragma unroll
            for (int d = 0; d < 32; d++) oacc[d] += e * vs[c0 + j][d];
        }
        m = mn;
    }
    float inv = 1.f / ssum;

    size_t ob = (size_t)p * 512 + (size_t)h * 32;
    __half2 hv[16];
    #pragma unroll
    for (int d = 0; d < 16; d++)
        hv[d] = __floats2half2_rn(oacc[2 * d] * inv, oacc[2 * d + 1] * inv);
    *(uint4*)(g_ah + ob)     = ((uint4*)hv)[0];
    *(uint4*)(g_ah + ob + 8) = ((uint4*)hv)[1];
    *(uint4*)(g_ah + ob + 16) = ((uint4*)hv)[2];
    *(uint4*)(g_ah + ob + 24) = ((uint4*)hv)[3];
}

// ---------------------------------------------------------------------------
// Launch
// ---------------------------------------------------------------------------
extern "C" void kernel_launch(void* const* d_in, const int* in_sizes, int n_in,
                              void* d_out, int out_size)
{
    const float* x     = (const float*)d_in[0];
    const float* ln_g  = (const float*)d_in[1];
    const float* ln_b  = (const float*)d_in[2];
    const float* w_qkv = (const float*)d_in[3];
    const float* w_out = (const float*)d_in[4];
    const float* b_out = (const float*)d_in[5];
    float* out = (float*)d_out;

    cudaFuncSetAttribute(gemm_hmma<0>, cudaFuncAttributeMaxDynamicSharedMemorySize, SM_GEMM);
    cudaFuncSetAttribute(gemm_hmma<1>, cudaFuncAttributeMaxDynamicSharedMemorySize, SM_GEMM);

    float *qkv;
    __half *xh, *ah, *wqhi, *wqlo, *wohi, *wolo;
    cudaGetSymbolAddress((void**)&qkv,  g_qkv);
    cudaGetSymbolAddress((void**)&xh,   g_xh);
    cudaGetSymbolAddress((void**)&ah,   g_ah);
    cudaGetSymbolAddress((void**)&wqhi, g_wqhi);
    cudaGetSymbolAddress((void**)&wqlo, g_wqlo);
    cudaGetSymbolAddress((void**)&wohi, g_wohi);
    cudaGetSymbolAddress((void**)&wolo, g_wolo);

    rope_init_kernel<<<1, 512>>>();
    convw_kernel<<<(E_QKV * KDIM + 255) / 256, 256>>>(w_qkv, wqhi, wqlo, E_QKV * KDIM);
    convw_kernel<<<(KDIM * KDIM + 255) / 256, 256>>>(w_out, wohi, wolo, KDIM * KDIM);
    ln_window_kernel<<<2048, 256>>>(x, ln_g, ln_b);

    {
        dim3 grid(E_QKV / 128, P_TOT / 128);   // (12, 512), bm fastest for L2 reuse
        gemm_hmma<0><<<grid, 256, SM_GEMM>>>(wqhi, wqlo, xh, qkv, nullptr, E_QKV);
    }

    {
        dim3 grid(NWIN, HEADS);
        attn_kernel<<<grid, 64>>>();
    }

    {
        dim3 grid(KDIM / 128, P_TOT / 128);    // (4, 512)
        gemm_hmma<1><<<grid, 256, SM_GEMM>>>(wohi, wolo, ah, out, b_out, 0);
    }
}

// round 9
// speedup vs baseline: 1.4264x; 1.0388x over previous
#include <cuda_runtime.h>
#include <cuda_fp16.h>
#include <math.h>
#include <stdint.h>

// ---------------------------------------------------------------------------
// Problem constants
// ---------------------------------------------------------------------------
#define P_TOT   65536            // B*H*W positions (windowed layout)
#define KDIM    512
#define E_QKV   1536
#define HEADS   16
#define L_WIN   64
#define NWIN    1024

// ---------------------------------------------------------------------------
// Scratch (static device globals: allocation-free)
// ---------------------------------------------------------------------------
__device__ __half g_xh [(size_t)P_TOT * KDIM];          // LN'd windowed input, [p][d] fp16
__device__ __half g_qkv[(size_t)P_TOT * E_QKV];         // qkv projection, [p][e] fp16
__device__ __half g_ah [(size_t)P_TOT * KDIM];          // attention out, [p][d] fp16
__device__ __half g_wqhi[E_QKV * KDIM], g_wqlo[E_QKV * KDIM];
__device__ __half g_wohi[KDIM * KDIM],  g_wolo[KDIM * KDIM];
__device__ float g_cos[L_WIN * 16];
__device__ float g_sin[L_WIN * 16];

// ---------------------------------------------------------------------------
// Helpers
// ---------------------------------------------------------------------------
__device__ __forceinline__ uint32_t smem_u32(const void* p) {
    uint32_t a;
    asm("{ .reg .u64 t; cvta.to.shared.u64 t, %1; cvt.u32.u64 %0, t; }" : "=r"(a) : "l"(p));
    return a;
}

__device__ __forceinline__ void cp16(uint32_t dst, const void* src) {
    asm volatile("cp.async.cg.shared.global [%0], [%1], 16;" :: "r"(dst), "l"(src));
}
__device__ __forceinline__ void cp_commit() {
    asm volatile("cp.async.commit_group;" ::: "memory");
}
template <int N>
__device__ __forceinline__ void cp_wait() {
    asm volatile("cp.async.wait_group %0;" :: "n"(N) : "memory");
}

__device__ __forceinline__ void ldm_x4(uint32_t* r, uint32_t addr) {
    asm volatile("ldmatrix.sync.aligned.m8n8.x4.shared.b16 {%0,%1,%2,%3}, [%4];"
                 : "=r"(r[0]), "=r"(r[1]), "=r"(r[2]), "=r"(r[3]) : "r"(addr));
}

__device__ __forceinline__ void mma_f16(float* c, const uint32_t* a, const uint32_t* b) {
    asm volatile(
        "mma.sync.aligned.m16n8k16.row.col.f32.f16.f16.f32 "
        "{%0,%1,%2,%3}, {%4,%5,%6,%7}, {%8,%9}, {%0,%1,%2,%3};"
        : "+f"(c[0]), "+f"(c[1]), "+f"(c[2]), "+f"(c[3])
        : "r"(a[0]), "r"(a[1]), "r"(a[2]), "r"(a[3]), "r"(b[0]), "r"(b[1]));
}

// load 32 consecutive halves -> fp32 regs
__device__ __forceinline__ void load32h(float* dst, const __half* src) {
    __half2 t[16];
    *(uint4*)(t)      = *(const uint4*)(src);
    *(uint4*)(t + 4)  = *(const uint4*)(src + 8);
    *(uint4*)(t + 8)  = *(const uint4*)(src + 16);
    *(uint4*)(t + 12) = *(const uint4*)(src + 24);
    #pragma unroll
    for (int d = 0; d < 16; d++) {
        float2 f = __half22float2(t[d]);
        dst[2 * d] = f.x; dst[2 * d + 1] = f.y;
    }
}

// ---------------------------------------------------------------------------
// RoPE table init
// ---------------------------------------------------------------------------
__global__ void rope_init_kernel() {
    int idx = threadIdx.x;
    for (; idx < L_WIN * 16; idx += blockDim.x) {
        int l = idx >> 4;
        int q = idx & 15;
        int i = l >> 3;
        int j = l & 7;
        float pos, e;
        if (q < 8) { pos = (float)i; e = (float)q; }
        else       { pos = (float)j; e = (float)(q - 8); }
        float freq  = powf(10000.0f, -e / 8.0f);
        float theta = pos * freq;
        g_cos[idx] = cosf(theta);
        g_sin[idx] = sinf(theta);
    }
}

// ---------------------------------------------------------------------------
// fp32 -> fp16 hi/lo split for weights (near-exact 2-term decomposition)
// ---------------------------------------------------------------------------
__global__ void convw_kernel(const float* __restrict__ w,
                             __half* __restrict__ hi,
                             __half* __restrict__ lo, int n) {
    int i = blockIdx.x * 256 + threadIdx.x;
    if (i < n) {
        float v = w[i];
        __half h = __float2half_rn(v);
        hi[i] = h;
        lo[i] = __float2half_rn(v - __half2float(h));
    }
}

// ---------------------------------------------------------------------------
// LayerNorm + roll(-4,-4) + window partition -> x fp16 in [p][d] layout
// ---------------------------------------------------------------------------
__global__ void __launch_bounds__(256) ln_window_kernel(
    const float* __restrict__ x,
    const float* __restrict__ ln_g,
    const float* __restrict__ ln_b)
{
    int blk = blockIdx.x;
    int w0  = (blk & 3) * 32;
    int h   = (blk >> 2) & 127;
    int bb  = blk >> 9;

    int px  = threadIdx.x & 31;
    int grp = threadIdx.x >> 5;
    int w   = w0 + px;

    __shared__ float sh_s[8][32], sh_s2[8][32];
    __shared__ float sh_m[32], sh_r[32];
    __shared__ int   sh_p[32];
    __shared__ float sh_g[512], sh_b[512];
    __shared__ float sh_t[32][132];

    for (int d = threadIdx.x; d < 512; d += 256) {
        sh_g[d] = ln_g[d];
        sh_b[d] = ln_b[d];
    }

    size_t base = (size_t)bb * (512u * 16384u) + (size_t)h * 128 + w;

    float vals[64];
    float s = 0.f, s2 = 0.f;
    #pragma unroll 8
    for (int i = 0; i < 64; i++) {
        float v = x[base + (size_t)(grp + 8 * i) * 16384];
        vals[i] = v;
        s += v; s2 += v * v;
    }

    sh_s[grp][px] = s; sh_s2[grp][px] = s2;
    if (grp == 0) {
        int hs  = (h - 4) & 127;
        int ws  = (w - 4) & 127;
        int wdx = bb * 256 + (hs >> 3) * 16 + (ws >> 3);
        sh_p[px] = wdx * 64 + (hs & 7) * 8 + (ws & 7);
    }
    __syncthreads();
    if (threadIdx.x < 32) {
        float ts = 0.f, ts2 = 0.f;
        #pragma unroll
        for (int g2 = 0; g2 < 8; g2++) { ts += sh_s[g2][threadIdx.x]; ts2 += sh_s2[g2][threadIdx.x]; }
        float mean = ts * (1.0f / 512.0f);
        float var  = ts2 * (1.0f / 512.0f) - mean * mean;
        sh_m[threadIdx.x] = mean;
        sh_r[threadIdx.x] = rsqrtf(var + 1e-5f);
    }
    __syncthreads();

    float mean = sh_m[px], r = sh_r[px];

    int pl = threadIdx.x >> 3;
    int jj = threadIdx.x & 7;

    for (int c = 0; c < 4; c++) {
        #pragma unroll
        for (int ii = 0; ii < 16; ii++) {
            int d = c * 128 + grp + 8 * ii;
            float xn = (vals[c * 16 + ii] - mean) * r * sh_g[d] + sh_b[d];
            sh_t[px][grp + 8 * ii] = xn;
        }
        __syncthreads();

        size_t dst = (size_t)sh_p[pl] * 512 + c * 128 + jj * 16;
        __half2 hv[8];
        #pragma unroll
        for (int t2 = 0; t2 < 8; t2++) {
            hv[t2] = __floats2half2_rn(sh_t[pl][jj * 16 + 2 * t2],
                                       sh_t[pl][jj * 16 + 2 * t2 + 1]);
        }
        *(uint4*)(g_xh + dst) = ((uint4*)hv)[0];
        *(uint4*)(g_xh + dst + 8) = ((uint4*)hv)[1];
        __syncthreads();
    }
}

// ---------------------------------------------------------------------------
// HMMA fp16 2-pass GEMM: C = (Ahi+Alo) * B^T  (A = weight split, B = fp16 act)
// CTA tile 128x128, BK=32, 8 warps (2x4), warp tile 64x32,
// 3-stage cp.async pipeline, leading + trailing barrier per chunk
// (trailing barrier is REQUIRED: stage (ch+3)%3 == ch%3 overwrite hazard).
// MODE 0: smem-transposed -> C[p][e] fp16. MODE 1: +bias, scatter fp32.
// ---------------------------------------------------------------------------
#define ROWB     80
#define OFF_AH   0
#define OFF_AL   (128 * ROWB)              // 10240
#define OFF_B    (2 * 128 * ROWB)          // 20480
#define STAGE_SZ (3 * 128 * ROWB)          // 30720
#define SM_GEMM  (3 * STAGE_SZ)            // 92160

template <int MODE>
__global__ void __launch_bounds__(256) gemm_hmma(
    const __half* __restrict__ Ahi, const __half* __restrict__ Alo,
    const __half* __restrict__ B,
    void* __restrict__ Cv, const float* __restrict__ bias, int EW)
{
    extern __shared__ __align__(128) char sm[];
    uint32_t smb = smem_u32(sm);

    const int tid  = threadIdx.x;
    const int wid  = tid >> 5;
    const int lane = tid & 31;
    const int bm   = blockIdx.x * 128;
    const int bn   = blockIdx.y * 128;
    const int wm   = (wid >> 2) * 64;
    const int wn   = (wid & 3) * 32;

    const int lrow = tid >> 2;           // 0..63
    const int lch  = (tid & 3) * 16;     // 0/16/32/48

    const char* pAh = (const char*)Ahi + (size_t)(bm + lrow) * 1024 + lch;
    const char* pAl = (const char*)Alo + (size_t)(bm + lrow) * 1024 + lch;
    const char* pB  = (const char*)B   + (size_t)(bn + lrow) * 1024 + lch;

    float acc[4][4][4];
    #pragma unroll
    for (int i = 0; i < 4; i++)
        #pragma unroll
        for (int j = 0; j < 4; j++)
            #pragma unroll
            for (int q = 0; q < 4; q++) acc[i][j][q] = 0.f;

    const int l7  = lane & 7;
    const int sel = lane >> 3;
    const int a_r = (sel & 1) * 8 + l7;
    const int a_k = (sel >> 1) * 16;
    const int b_r = (sel >> 1) * 8 + l7;
    const int b_k = (sel & 1) * 16;

    auto load_stage = [&](int ch, int st) {
        const size_t gk = (size_t)ch * 64;
        uint32_t sb = smb + st * STAGE_SZ;
        #pragma unroll
        for (int r = 0; r < 2; r++) {
            int row = lrow + r * 64;
            uint32_t dof = row * ROWB + lch;
            size_t   sof = gk + (size_t)r * 64 * 1024;
            cp16(sb + OFF_AH + dof, pAh + sof);
            cp16(sb + OFF_AL + dof, pAl + sof);
            cp16(sb + OFF_B  + dof, pB  + sof);
        }
        cp_commit();
    };

    load_stage(0, 0);
    load_stage(1, 1);

    #pragma unroll 1
    for (int ch = 0; ch < 16; ch++) {
        if (ch < 14) {
            load_stage(ch + 2, (ch + 2) % 3);
            cp_wait<2>();
        } else if (ch == 14) {
            cp_wait<1>();
        } else {
            cp_wait<0>();
        }
        __syncthreads();

        uint32_t sb  = smb + (ch % 3) * STAGE_SZ;
        uint32_t aAH = sb + OFF_AH + (wm + a_r) * ROWB + a_k;
        uint32_t aAL = sb + OFF_AL + (wm + a_r) * ROWB + a_k;
        uint32_t aB  = sb + OFF_B  + (wn + b_r) * ROWB + b_k;

        #pragma unroll
        for (int ks = 0; ks < 2; ks++) {
            int kb = ks * 32;
            uint32_t ah[4][4], al[4][4], bf[4][2];
            #pragma unroll
            for (int mt = 0; mt < 4; mt++) {
                ldm_x4(ah[mt], aAH + mt * (16 * ROWB) + kb);
                ldm_x4(al[mt], aAL + mt * (16 * ROWB) + kb);
            }
            #pragma unroll
            for (int np = 0; np < 2; np++) {
                uint32_t t4[4];
                ldm_x4(t4, aB + np * (16 * ROWB) + kb);
                bf[2 * np][0] = t4[0]; bf[2 * np][1] = t4[1];
                bf[2 * np + 1][0] = t4[2]; bf[2 * np + 1][1] = t4[3];
            }
            #pragma unroll
            for (int mt = 0; mt < 4; mt++)
                #pragma unroll
                for (int nt = 0; nt < 4; nt++)
                    mma_f16(acc[mt][nt], ah[mt], bf[nt]);
            #pragma unroll
            for (int mt = 0; mt < 4; mt++)
                #pragma unroll
                for (int nt = 0; nt < 4; nt++)
                    mma_f16(acc[mt][nt], al[mt], bf[nt]);
        }
        __syncthreads();   // REQUIRED: next iteration's load_stage reuses this stage
    }

    // ------------------------------ epilogue ------------------------------
    const int mrow0 = bm + wm + (lane >> 2);
    const int ncol0 = bn + wn + (lane & 3) * 2;

    if (MODE == 0) {
        // transpose through smem -> fp16 C[p][e], row width EW
        float* smt = (float*)sm;   // [128 p][132 e]
        #pragma unroll
        for (int mt = 0; mt < 4; mt++) {
            #pragma unroll
            for (int nt = 0; nt < 4; nt++) {
                int e0  = wm + (lane >> 2) + mt * 16;
                int pl0 = wn + (lane & 3) * 2 + nt * 8;
                smt[(pl0)     * 132 + e0]     = acc[mt][nt][0];
                smt[(pl0 + 1) * 132 + e0]     = acc[mt][nt][1];
                smt[(pl0)     * 132 + e0 + 8] = acc[mt][nt][2];
                smt[(pl0 + 1) * 132 + e0 + 8] = acc[mt][nt][3];
            }
        }
        __syncthreads();
        __half* Ch = (__half*)Cv;
        int colb = (tid & 15) * 8;
        int rowb = tid >> 4;          // 0..15
        #pragma unroll
        for (int i = 0; i < 8; i++) {
            int row = rowb + i * 16;
            float4 v0 = *(float4*)&smt[row * 132 + colb];
            float4 v1 = *(float4*)&smt[row * 132 + colb + 4];
            __half2 hv[4];
            hv[0] = __floats2half2_rn(v0.x, v0.y);
            hv[1] = __floats2half2_rn(v0.z, v0.w);
            hv[2] = __floats2half2_rn(v1.x, v1.y);
            hv[3] = __floats2half2_rn(v1.z, v1.w);
            *(uint4*)(Ch + (size_t)(bn + row) * EW + bm + colb) = *(uint4*)hv;
        }
    } else {
        float* C = (float*)Cv;
        #pragma unroll
        for (int mt = 0; mt < 4; mt++) {
            float bo0 = bias[mrow0 + mt * 16];
            float bo1 = bias[mrow0 + mt * 16 + 8];
            #pragma unroll
            for (int nt = 0; nt < 4; nt++) {
                int p   = ncol0 + nt * 8;       // even; p+1 in same window row
                int wdx = p >> 6, l = p & 63;
                int bb  = wdx >> 8, rem = wdx & 255;
                int hs  = ((rem >> 4) << 3) + (l >> 3);
                int ws  = ((rem & 15) << 3) + (l & 7);
                int hh  = (hs + 4) & 127;
                int ww  = (ws + 4) & 127;
                #pragma unroll
                for (int qh = 0; qh < 2; qh++) {
                    int m = mrow0 + mt * 16 + qh * 8;
                    float bo = qh ? bo1 : bo0;
                    size_t idx = (((size_t)bb * 512 + m) << 14) + (hh << 7) + ww;
                    *(float2*)(C + idx) =
                        make_float2(acc[mt][nt][2 * qh] + bo, acc[mt][nt][2 * qh + 1] + bo);
                }
            }
        }
    }
}

// ---------------------------------------------------------------------------
// Attention per (window, head). Reads fp16 g_qkv [p][e]; writes fp16 [p][d].
// 64 threads; thread t owns position row p0+t. 4-chunk flash softmax.
// ---------------------------------------------------------------------------
__global__ void __launch_bounds__(64) attn_kernel() {
    int win = blockIdx.x;
    int h   = blockIdx.y;
    int t   = threadIdx.x;

    __shared__ float ks[L_WIN][36];
    __shared__ float vs[L_WIN][36];

    int p = win * 64 + t;
    const __half* rowq = g_qkv + (size_t)p * E_QKV + h * 32;

    float qr[32];
    load32h(qr, rowq);

    {
        float kr[32], vr[32];
        load32h(kr, rowq + 512);
        load32h(vr, rowq + 1024);

        const float scale = 0.17677669529663687f;   // 32^-0.5
        #pragma unroll
        for (int d = 0; d < 16; d++) {
            float c = g_cos[t * 16 + d];
            float s = g_sin[t * 16 + d];
            float q1 = qr[d], q2 = qr[d + 16];
            qr[d]      = (q1 * c - q2 * s) * scale;
            qr[d + 16] = (q2 * c + q1 * s) * scale;
            float k1 = kr[d], k2 = kr[d + 16];
            kr[d]      = k1 * c - k2 * s;
            kr[d + 16] = k2 * c + k1 * s;
        }
        #pragma unroll
        for (int d = 0; d < 32; d++) { ks[t][d] = kr[d]; vs[t][d] = vr[d]; }
    }
    __syncthreads();

    float m = -1e30f, ssum = 0.f;
    float oacc[32];
    #pragma unroll
    for (int d = 0; d < 32; d++) oacc[d] = 0.f;

    #pragma unroll 1
    for (int c0 = 0; c0 < 64; c0 += 16) {
        float lo[16];
        float mc = -1e30f;
        #pragma unroll
        for (int j = 0; j < 16; j++) {
            float s = 0.f;
            #pragma unroll
            for (int d = 0; d < 32; d++) s += qr[d] * ks[c0 + j][d];
            lo[j] = s;
            mc = fmaxf(mc, s);
        }
        float mn = fmaxf(m, mc);
        float f  = __expf(m - mn);
        ssum *= f;
        #pragma unroll
        for (int d = 0; d < 32; d++) oacc[d] *= f;
        #pragma unroll
        for (int j = 0; j < 16; j++) {
            float e = __expf(lo[j] - mn);
            ssum += e;
            #pragma unroll
            for (int d = 0; d < 32; d++) oacc[d] += e * vs[c0 + j][d];
        }
        m = mn;
    }
    float inv = 1.f / ssum;

    size_t ob = (size_t)p * 512 + (size_t)h * 32;
    __half2 hv[16];
    #pragma unroll
    for (int d = 0; d < 16; d++)
        hv[d] = __floats2half2_rn(oacc[2 * d] * inv, oacc[2 * d + 1] * inv);
    *(uint4*)(g_ah + ob)      = ((uint4*)hv)[0];
    *(uint4*)(g_ah + ob + 8)  = ((uint4*)hv)[1];
    *(uint4*)(g_ah + ob + 16) = ((uint4*)hv)[2];
    *(uint4*)(g_ah + ob + 24) = ((uint4*)hv)[3];
}

// ---------------------------------------------------------------------------
// Launch
// ---------------------------------------------------------------------------
extern "C" void kernel_launch(void* const* d_in, const int* in_sizes, int n_in,
                              void* d_out, int out_size)
{
    const float* x     = (const float*)d_in[0];
    const float* ln_g  = (const float*)d_in[1];
    const float* ln_b  = (const float*)d_in[2];
    const float* w_qkv = (const float*)d_in[3];
    const float* w_out = (const float*)d_in[4];
    const float* b_out = (const float*)d_in[5];
    float* out = (float*)d_out;

    cudaFuncSetAttribute(gemm_hmma<0>, cudaFuncAttributeMaxDynamicSharedMemorySize, SM_GEMM);
    cudaFuncSetAttribute(gemm_hmma<1>, cudaFuncAttributeMaxDynamicSharedMemorySize, SM_GEMM);

    __half *qkv, *xh, *ah, *wqhi, *wqlo, *wohi, *wolo;
    cudaGetSymbolAddress((void**)&qkv,  g_qkv);
    cudaGetSymbolAddress((void**)&xh,   g_xh);
    cudaGetSymbolAddress((void**)&ah,   g_ah);
    cudaGetSymbolAddress((void**)&wqhi, g_wqhi);
    cudaGetSymbolAddress((void**)&wqlo, g_wqlo);
    cudaGetSymbolAddress((void**)&wohi, g_wohi);
    cudaGetSymbolAddress((void**)&wolo, g_wolo);

    rope_init_kernel<<<1, 512>>>();
    convw_kernel<<<(E_QKV * KDIM + 255) / 256, 256>>>(w_qkv, wqhi, wqlo, E_QKV * KDIM);
    convw_kernel<<<(KDIM * KDIM + 255) / 256, 256>>>(w_out, wohi, wolo, KDIM * KDIM);
    ln_window_kernel<<<2048, 256>>>(x, ln_g, ln_b);

    {
        dim3 grid(E_QKV / 128, P_TOT / 128);   // (12, 512), bm fastest for L2 reuse
        gemm_hmma<0><<<grid, 256, SM_GEMM>>>(wqhi, wqlo, xh, qkv, nullptr, E_QKV);
    }

    {
        dim3 grid(NWIN, HEADS);
        attn_kernel<<<grid, 64>>>();
    }

    {
        dim3 grid(KDIM / 128, P_TOT / 128);    // (4, 512)
        gemm_hmma<1><<<grid, 256, SM_GEMM>>>(wohi, wolo, ah, out, b_out, 0);
    }
}